// round 7
// baseline (speedup 1.0000x reference)
#include <cuda_runtime.h>

// Problem constants: B=2, N=1024, T=64, H=64
#define NN 1024

// Scratch (allocation-free rule: __device__ globals)
// p/q layout: [h][n][b] interleaved -> element (h,n,b) at (h*1024+n)*2+b
__device__ float g_p[2 * 64 * NN];
__device__ float g_q[2 * 64 * NN];
__device__ float g_U[NN];
__device__ float g_V[NN];
__device__ float g_pv[NN * 16];      // per-(row, col-tile) partial max value
__device__ int   g_pi[NN * 16];      // per-(row, col-tile) partial argmax j
// cross-block sync state (reset to 0 by the last block each run)
__device__ int   g_flag[16];         // per 64-node slice: # of producer blocks done
__device__ int   g_rowcnt[16];       // per row-tile: # of consumer blocks done
__device__ int   g_done;             // global completion counter

// ---------------------------------------------------------------------------
// Single fused kernel. 256 blocks x 256 threads.
// Phase A (all blocks): produce p,q,U,V for 4 nodes [4*bid, 4*bid+4).
// Phase B: wait for the 2 slice flags this block consumes, then pairwise
//          |z| accumulation + gumbel + per-tile argmax partials.
// Phase C: last block per row-tile reduces partials + scatters one-hot 1.0s;
//          last block overall resets counters.
// ---------------------------------------------------------------------------
__global__ void __launch_bounds__(256, 2) mega(
    const float* __restrict__ x, const float* __restrict__ W1,
    const float* __restrict__ b1, const float* __restrict__ W2,
    const float* __restrict__ b2, const float* __restrict__ gu,
    float* __restrict__ out) {
    // smem pool, aliased between phases:
    //  producer: sW[64][132] (8448 f) | sx[2][4][68] (544 f) | sUV (16 f)
    //  consumer: ps[32][128] (4096 f) | qs[32][128] (4096 f) | sw (64 f)
    __shared__ __align__(16) float pool[9024];
    __shared__ int s_old;

    float (*sW)[132]   = (float(*)[132])pool;
    float (*sx)[4][68] = (float(*)[4][68])(pool + 8448);
    float *sUV         = pool + 8448 + 544;
    float (*ps)[128]   = (float(*)[128])pool;
    float (*qs)[128]   = (float(*)[128])(pool + 4096);
    float *sw          = pool + 8192;

    const int tid = threadIdx.x;
    const int bid = blockIdx.x;          // 0..255
    const int bx = bid & 15, by = bid >> 4;

    // ===================== Phase A: produce 4 nodes =====================
    {
        const int n0p = bid * 4;
        #pragma unroll
        for (int k = 0; k < 32; ++k) {           // W1: 8192 floats -> sW
            int l = k * 256 + tid;
            sW[l >> 7][l & 127] = W1[l];
        }
        #pragma unroll
        for (int k = 0; k < 2; ++k) {            // x: 512 floats
            int l = k * 256 + tid;
            int b = l >> 8, node = (l >> 6) & 3, t = l & 63;
            sx[b][node][t] = x[((b << 10) + n0p + node) * 64 + t];
        }
        __syncthreads();

        const int h = tid & 63, nn = tid >> 6;
        float p0 = 0.f, p1 = 0.f, q0 = 0.f, q1 = 0.f;
        #pragma unroll 4
        for (int t = 0; t < 64; t += 4) {
            float4 wa = *(const float4*)&sW[h][t];
            float4 wb = *(const float4*)&sW[h][64 + t];
            float4 xa = *(const float4*)&sx[0][nn][t];
            float4 xb = *(const float4*)&sx[1][nn][t];
            p0 = fmaf(xa.x, wa.x, p0); p0 = fmaf(xa.y, wa.y, p0);
            p0 = fmaf(xa.z, wa.z, p0); p0 = fmaf(xa.w, wa.w, p0);
            p1 = fmaf(xb.x, wa.x, p1); p1 = fmaf(xb.y, wa.y, p1);
            p1 = fmaf(xb.z, wa.z, p1); p1 = fmaf(xb.w, wa.w, p1);
            q0 = fmaf(xa.x, wb.x, q0); q0 = fmaf(xa.y, wb.y, q0);
            q0 = fmaf(xa.z, wb.z, q0); q0 = fmaf(xa.w, wb.w, q0);
            q1 = fmaf(xb.x, wb.x, q1); q1 = fmaf(xb.y, wb.y, q1);
            q1 = fmaf(xb.z, wb.z, q1); q1 = fmaf(xb.w, wb.w, q1);
        }
        float bb = __ldg(&b1[h]);
        q0 += bb; q1 += bb;

        *(float2*)&g_p[(h * 1024 + n0p + nn) * 2] = make_float2(p0, p1);
        *(float2*)&g_q[(h * 1024 + n0p + nn) * 2] = make_float2(q0, q1);

        // U/V: warp shuffle reduce over h (2 warps per node)
        float w2h = __ldg(&W2[h]);
        float ru = w2h * (p0 + p1), rv = w2h * (q0 + q1);
        #pragma unroll
        for (int m = 16; m > 0; m >>= 1) {
            ru += __shfl_down_sync(0xffffffffu, ru, m);
            rv += __shfl_down_sync(0xffffffffu, rv, m);
        }
        if ((tid & 31) == 0) {
            int w = tid >> 5;                    // warp 0..7, node = w>>1
            sUV[w] = ru; sUV[8 + w] = rv;
        }
        __syncthreads();
        if (tid < 4) {
            g_U[n0p + tid] = 0.2525f * (sUV[2 * tid] + sUV[2 * tid + 1]);
            g_V[n0p + tid] = 0.2525f * (sUV[8 + 2 * tid] + sUV[9 + 2 * tid])
                             + __ldg(&b2[0]);
        }
        __threadfence();
        __syncthreads();
        if (tid == 0) atomicAdd(&g_flag[bid >> 4], 1);
    }

    // ===================== Phase B: wait + pairwise core =====================
    if (tid == 0) {
        volatile int* vf = g_flag;
        while (vf[by] < 16 || vf[bx] < 16) __nanosleep(64);
        __threadfence();   // acquire
    }
    __syncthreads();       // broadcast readiness; also retires producer smem use

    const int tx = tid & 15, ty = tid >> 4;
    const int i0 = by * 64, j0 = bx * 64;

    if (tid < 64) sw[tid] = 0.2475f * W2[tid];

    float acc[4][4];
    #pragma unroll
    for (int r = 0; r < 4; ++r)
        #pragma unroll
        for (int c = 0; c < 4; ++c) acc[r][c] = 0.f;

    #pragma unroll
    for (int hc = 0; hc < 2; ++hc) {
        const int hb = hc * 32;
        const float* __restrict__ pgc = g_p + (hb * 1024 + i0) * 2;
        const float* __restrict__ qgc = g_q + (hb * 1024 + j0) * 2;
        __syncthreads();   // protect prior chunk (and sw on first iter)
        #pragma unroll
        for (int k = 0; k < 4; ++k) {
            int l = k * 256 + tid;               // 0..1023 float4 idx
            int hh = l >> 5, f4 = l & 31;
            *(float4*)&ps[hh][f4 << 2] = *(const float4*)&pgc[hh * 2048 + (f4 << 2)];
            *(float4*)&qs[hh][f4 << 2] = *(const float4*)&qgc[hh * 2048 + (f4 << 2)];
        }
        __syncthreads();

        #pragma unroll 4
        for (int h = 0; h < 32; ++h) {
            float w = sw[hb + h];
            float4 pA = *(const float4*)&ps[h][ty << 3];
            float4 pB = *(const float4*)&ps[h][(ty << 3) + 4];
            float4 qA = *(const float4*)&qs[h][tx << 3];
            float4 qB = *(const float4*)&qs[h][(tx << 3) + 4];
            float pv[8] = {pA.x, pA.y, pA.z, pA.w, pB.x, pB.y, pB.z, pB.w};
            float qv[8] = {qA.x, qA.y, qA.z, qA.w, qB.x, qB.y, qB.z, qB.w};
            #pragma unroll
            for (int r = 0; r < 4; ++r)
                #pragma unroll
                for (int c = 0; c < 4; ++c) {
                    float z0 = pv[2 * r]     + qv[2 * c];
                    float z1 = pv[2 * r + 1] + qv[2 * c + 1];
                    acc[r][c] = fmaf(w, fabsf(z0), acc[r][c]);
                    acc[r][c] = fmaf(w, fabsf(z1), acc[r][c]);
                }
        }
    }

    float u[4], v[4];
    #pragma unroll
    for (int r = 0; r < 4; ++r) u[r] = g_U[i0 + (ty << 2) + r];
    #pragma unroll
    for (int c = 0; c < 4; ++c) v[c] = g_V[j0 + (tx << 2) + c];

    float vrow[4][4];
    #pragma unroll
    for (int r = 0; r < 4; ++r)
        #pragma unroll
        for (int c = 0; c < 4; ++c)
            vrow[r][c] = acc[r][c] + u[r] + v[c];

    // zero-fill this out tile (final ones written in Phase C)
    const float4 z4 = make_float4(0.f, 0.f, 0.f, 0.f);
    #pragma unroll
    for (int r = 0; r < 4; ++r)
        *(float4*)&out[(i0 + (ty << 2) + r) * 1024 + j0 + (tx << 2)] = z4;

    // gumbel + per-row argmax across the 16 tx lanes
    #pragma unroll
    for (int r = 0; r < 4; ++r) {
        const int row = i0 + (ty << 2) + r;
        float4 uu = *(const float4*)&gu[row * 1024 + j0 + (tx << 2)];
        float gq[4];
        gq[0] = -__logf(-__logf(uu.x + 1e-10f) + 1e-10f);
        gq[1] = -__logf(-__logf(uu.y + 1e-10f) + 1e-10f);
        gq[2] = -__logf(-__logf(uu.z + 1e-10f) + 1e-10f);
        gq[3] = -__logf(-__logf(uu.w + 1e-10f) + 1e-10f);
        float bv = -3.0e38f; int bj = 1 << 30;
        #pragma unroll
        for (int c = 0; c < 4; ++c) {
            float val = vrow[r][c] + gq[c];
            int j = j0 + (tx << 2) + c;
            if (val > bv || (val == bv && j < bj)) { bv = val; bj = j; }
        }
        #pragma unroll
        for (int m = 1; m < 16; m <<= 1) {
            float ov = __shfl_xor_sync(0xffffffffu, bv, m);
            int   oj = __shfl_xor_sync(0xffffffffu, bj, m);
            if (ov > bv || (ov == bv && oj < bj)) { bv = ov; bj = oj; }
        }
        if (tx == 0) {
            g_pv[row * 16 + bx] = bv;
            g_pi[row * 16 + bx] = bj;
        }
    }

    // ===================== Phase C: row-tile finisher =====================
    __threadfence();
    __syncthreads();
    if (tid == 0) s_old = atomicAdd(&g_rowcnt[by], 1);
    __syncthreads();
    if (s_old == 15) {                 // this block is 16th for row-tile `by`
        __threadfence();               // see all partials
        if (tid < 64) {
            const int row = by * 64 + tid;
            float bv = -3.0e38f; int bj = 1 << 30;
            #pragma unroll
            for (int k4 = 0; k4 < 4; ++k4) {
                float4 v4 = *(const float4*)&g_pv[row * 16 + k4 * 4];
                int4   j4 = *(const int4*)&g_pi[row * 16 + k4 * 4];
                float vv[4] = {v4.x, v4.y, v4.z, v4.w};
                int   jj[4] = {j4.x, j4.y, j4.z, j4.w};
                #pragma unroll
                for (int k = 0; k < 4; ++k)
                    if (vv[k] > bv || (vv[k] == bv && jj[k] < bj)) { bv = vv[k]; bj = jj[k]; }
            }
            out[row * 1024 + bj] = 1.0f;
        }
    }

    // last block overall resets the sync state for the next graph replay
    if (tid == 0) {
        int old2 = atomicAdd(&g_done, 1);
        if (old2 == 255) {
            #pragma unroll
            for (int s = 0; s < 16; ++s) { g_flag[s] = 0; g_rowcnt[s] = 0; }
            g_done = 0;
        }
    }
}

// ---------------------------------------------------------------------------
extern "C" void kernel_launch(void* const* d_in, const int* in_sizes, int n_in,
                              void* d_out, int out_size) {
    const float* x  = (const float*)d_in[0];   // [2,1024,64]
    const float* W1 = (const float*)d_in[1];   // [64,128]
    const float* b1 = (const float*)d_in[2];   // [64]
    const float* W2 = (const float*)d_in[3];   // [1,64]
    const float* b2 = (const float*)d_in[4];   // [1]
    const float* gu = (const float*)d_in[5];   // [1024,1024]
    float* out = (float*)d_out;                // [1024,1024] fp32

    mega<<<256, 256>>>(x, W1, b1, W2, b2, gu, out);
}

// round 8
// speedup vs baseline: 1.0123x; 1.0123x over previous
#include <cuda_runtime.h>

// Problem constants: B=2, N=1024, T=64, H=64
#define NN 1024

// Scratch (allocation-free rule: __device__ globals)
// p/q layout: [h][n][b] interleaved -> element (h,n,b) at (h*1024+n)*2+b
__device__ float g_p[2 * 64 * NN];
__device__ float g_q[2 * 64 * NN];
__device__ float g_U[NN];
__device__ float g_V[NN];
__device__ float g_pv[NN * 16];      // per-(row, col-tile) partial max value
__device__ int   g_pi[NN * 16];      // per-(row, col-tile) partial argmax j
// cross-block tail state (reset by last k2 block each run)
__device__ int   g_rowcnt[16];
__device__ int   g_done;

// ---------------------------------------------------------------------------
// Kernel 1: per-node projections. 256 blocks x 256 threads, 4 nodes/block.
// Thread = (h = tid>>2, nn = tid&3). W1 read directly from gmem (L1-cached,
// 4-lane broadcast) -- no smem staging, no pre-compute sync.
//   p[h,n,b] = sum_t x[b,n,t]*W1[h,t]
//   q[h,n,b] = sum_t x[b,n,t]*W1[h,64+t] + b1[h]
//   U[n] = 0.2525*sum_{b,h} w2[h]*p ;  V[n] = 0.2525*sum_{b,h} w2[h]*q + b2
// ---------------------------------------------------------------------------
__global__ void __launch_bounds__(256) k1_proj(
    const float* __restrict__ x, const float* __restrict__ W1,
    const float* __restrict__ b1, const float* __restrict__ W2,
    const float* __restrict__ b2) {
    __shared__ __align__(16) float sx[2][4][68];   // x rows, pitch 68
    __shared__ float sUV[2][32];                   // warp partials [sel][w*4+nn]

    const int tid = threadIdx.x;
    const int n0 = blockIdx.x * 4;

    #pragma unroll
    for (int k = 0; k < 2; ++k) {             // x: 512 floats
        int l = k * 256 + tid;
        int b = l >> 8, node = (l >> 6) & 3, t = l & 63;
        sx[b][node][t] = x[((b << 10) + n0 + node) * 64 + t];
    }
    __syncthreads();

    const int h = tid >> 2;       // 0..63
    const int nn = tid & 3;       // 0..3
    const float4* __restrict__ wrow = (const float4*)(W1 + h * 128);

    float p0 = 0.f, p1 = 0.f, q0 = 0.f, q1 = 0.f;
    #pragma unroll
    for (int tt = 0; tt < 16; ++tt) {
        float4 wa = __ldg(&wrow[tt]);
        float4 wb = __ldg(&wrow[16 + tt]);
        float4 xa = *(const float4*)&sx[0][nn][tt * 4];
        float4 xb = *(const float4*)&sx[1][nn][tt * 4];
        p0 = fmaf(xa.x, wa.x, p0); p0 = fmaf(xa.y, wa.y, p0);
        p0 = fmaf(xa.z, wa.z, p0); p0 = fmaf(xa.w, wa.w, p0);
        p1 = fmaf(xb.x, wa.x, p1); p1 = fmaf(xb.y, wa.y, p1);
        p1 = fmaf(xb.z, wa.z, p1); p1 = fmaf(xb.w, wa.w, p1);
        q0 = fmaf(xa.x, wb.x, q0); q0 = fmaf(xa.y, wb.y, q0);
        q0 = fmaf(xa.z, wb.z, q0); q0 = fmaf(xa.w, wb.w, q0);
        q1 = fmaf(xb.x, wb.x, q1); q1 = fmaf(xb.y, wb.y, q1);
        q1 = fmaf(xb.z, wb.z, q1); q1 = fmaf(xb.w, wb.w, q1);
    }
    float bb = __ldg(&b1[h]);
    q0 += bb; q1 += bb;

    *(float2*)&g_p[(h * 1024 + n0 + nn) * 2] = make_float2(p0, p1);
    *(float2*)&g_q[(h * 1024 + n0 + nn) * 2] = make_float2(q0, q1);

    // U/V: reduce over the 8 h-values within each warp (lanes with same nn)
    float w2h = __ldg(&W2[h]);
    float ru = w2h * (p0 + p1), rv = w2h * (q0 + q1);
    #pragma unroll
    for (int m = 16; m >= 4; m >>= 1) {
        ru += __shfl_down_sync(0xffffffffu, ru, m);
        rv += __shfl_down_sync(0xffffffffu, rv, m);
    }
    if ((tid & 31) < 4) {
        int w = tid >> 5;
        sUV[0][w * 4 + nn] = ru;
        sUV[1][w * 4 + nn] = rv;
    }
    __syncthreads();
    if (tid < 8) {
        int sel = tid >> 2, n2 = tid & 3;
        float acc = 0.f;
        #pragma unroll
        for (int w = 0; w < 8; ++w) acc += sUV[sel][w * 4 + n2];
        if (sel == 0) g_U[n0 + n2] = 0.2525f * acc;
        else          g_V[n0 + n2] = 0.2525f * acc + __ldg(&b2[0]);
    }
}

// ---------------------------------------------------------------------------
// Kernel 2: pairwise |z| accumulation (scalar FADD + FFMA|.|) + fused
// gumbel/argmax + fused finisher tail (atomic ticket per row-tile).
//   logit[i,j] = sum_{b,h} 0.2475*w2[h]*|p[h,i,b]+q[h,j,b]| + U[i] + V[j]
// Grid 16x16 (64x64 tile), block 16x16 threads, 4i x 4j x 2b per thread.
// ---------------------------------------------------------------------------
__global__ void __launch_bounds__(256) k2_pair(const float* __restrict__ W2,
                                               const float* __restrict__ gu,
                                               float* __restrict__ out) {
    __shared__ __align__(16) float ps[32][128];    // [h][i*2+b] chunk
    __shared__ __align__(16) float qs[32][128];    // [h][j*2+b] chunk
    __shared__ float sw[64];
    __shared__ int s_old;

    const int tx = threadIdx.x, ty = threadIdx.y;
    const int tid = ty * 16 + tx;
    const int bx = blockIdx.x, by = blockIdx.y;
    const int i0 = by * 64, j0 = bx * 64;

    if (tid < 64) sw[tid] = 0.2475f * W2[tid];

    float acc[4][4];
    #pragma unroll
    for (int r = 0; r < 4; ++r)
        #pragma unroll
        for (int c = 0; c < 4; ++c) acc[r][c] = 0.f;

    #pragma unroll
    for (int hc = 0; hc < 2; ++hc) {
        const int hb = hc * 32;
        const float* __restrict__ pgc = g_p + (hb * 1024 + i0) * 2;
        const float* __restrict__ qgc = g_q + (hb * 1024 + j0) * 2;
        __syncthreads();   // protect prior chunk (and sw on first iter)
        #pragma unroll
        for (int k = 0; k < 4; ++k) {
            int l = k * 256 + tid;               // 0..1023 float4 idx
            int hh = l >> 5, f4 = l & 31;
            *(float4*)&ps[hh][f4 << 2] = *(const float4*)&pgc[hh * 2048 + (f4 << 2)];
            *(float4*)&qs[hh][f4 << 2] = *(const float4*)&qgc[hh * 2048 + (f4 << 2)];
        }
        __syncthreads();

        #pragma unroll 4
        for (int h = 0; h < 32; ++h) {
            float w = sw[hb + h];
            float4 pA = *(const float4*)&ps[h][ty << 3];
            float4 pB = *(const float4*)&ps[h][(ty << 3) + 4];
            float4 qA = *(const float4*)&qs[h][tx << 3];
            float4 qB = *(const float4*)&qs[h][(tx << 3) + 4];
            float pv[8] = {pA.x, pA.y, pA.z, pA.w, pB.x, pB.y, pB.z, pB.w};
            float qv[8] = {qA.x, qA.y, qA.z, qA.w, qB.x, qB.y, qB.z, qB.w};
            #pragma unroll
            for (int r = 0; r < 4; ++r)
                #pragma unroll
                for (int c = 0; c < 4; ++c) {
                    float z0 = pv[2 * r]     + qv[2 * c];
                    float z1 = pv[2 * r + 1] + qv[2 * c + 1];
                    acc[r][c] = fmaf(w, fabsf(z0), acc[r][c]);
                    acc[r][c] = fmaf(w, fabsf(z1), acc[r][c]);
                }
        }
    }

    float u[4], v[4];
    #pragma unroll
    for (int r = 0; r < 4; ++r) u[r] = g_U[i0 + (ty << 2) + r];
    #pragma unroll
    for (int c = 0; c < 4; ++c) v[c] = g_V[j0 + (tx << 2) + c];

    float vrow[4][4];
    #pragma unroll
    for (int r = 0; r < 4; ++r)
        #pragma unroll
        for (int c = 0; c < 4; ++c)
            vrow[r][c] = acc[r][c] + u[r] + v[c];

    // zero-fill this out tile (final ones written by the finisher tail)
    const float4 z4 = make_float4(0.f, 0.f, 0.f, 0.f);
    #pragma unroll
    for (int r = 0; r < 4; ++r)
        *(float4*)&out[(i0 + (ty << 2) + r) * 1024 + j0 + (tx << 2)] = z4;

    // gumbel + per-row argmax across the 16 tx lanes
    #pragma unroll
    for (int r = 0; r < 4; ++r) {
        const int row = i0 + (ty << 2) + r;
        float4 uu = *(const float4*)&gu[row * 1024 + j0 + (tx << 2)];
        float gq[4];
        gq[0] = -__logf(-__logf(uu.x + 1e-10f) + 1e-10f);
        gq[1] = -__logf(-__logf(uu.y + 1e-10f) + 1e-10f);
        gq[2] = -__logf(-__logf(uu.z + 1e-10f) + 1e-10f);
        gq[3] = -__logf(-__logf(uu.w + 1e-10f) + 1e-10f);
        float bv = -3.0e38f; int bj = 1 << 30;
        #pragma unroll
        for (int c = 0; c < 4; ++c) {
            float val = vrow[r][c] + gq[c];
            int j = j0 + (tx << 2) + c;
            if (val > bv || (val == bv && j < bj)) { bv = val; bj = j; }
        }
        #pragma unroll
        for (int m = 1; m < 16; m <<= 1) {
            float ov = __shfl_xor_sync(0xffffffffu, bv, m);
            int   oj = __shfl_xor_sync(0xffffffffu, bj, m);
            if (ov > bv || (ov == bv && oj < bj)) { bv = ov; bj = oj; }
        }
        if (tx == 0) {
            g_pv[row * 16 + bx] = bv;
            g_pi[row * 16 + bx] = bj;
        }
    }

    // ------- finisher tail: 16th block of row-tile reduces + scatters -------
    __threadfence();
    __syncthreads();
    if (tid == 0) s_old = atomicAdd(&g_rowcnt[by], 1);
    __syncthreads();
    if (s_old == 15) {
        __threadfence();               // see all partials + zero-fills
        if (tid < 64) {
            const int row = by * 64 + tid;
            float bv = -3.0e38f; int bj = 1 << 30;
            #pragma unroll
            for (int k4 = 0; k4 < 4; ++k4) {
                float4 v4 = *(const float4*)&g_pv[row * 16 + k4 * 4];
                int4   j4 = *(const int4*)&g_pi[row * 16 + k4 * 4];
                float vv[4] = {v4.x, v4.y, v4.z, v4.w};
                int   jj[4] = {j4.x, j4.y, j4.z, j4.w};
                #pragma unroll
                for (int k = 0; k < 4; ++k)
                    if (vv[k] > bv || (vv[k] == bv && jj[k] < bj)) { bv = vv[k]; bj = jj[k]; }
            }
            out[row * 1024 + bj] = 1.0f;
        }
    }
    // last block overall resets tail state for the next graph replay
    if (tid == 0) {
        int old2 = atomicAdd(&g_done, 1);
        if (old2 == 255) {
            #pragma unroll
            for (int s = 0; s < 16; ++s) g_rowcnt[s] = 0;
            g_done = 0;
        }
    }
}

// ---------------------------------------------------------------------------
extern "C" void kernel_launch(void* const* d_in, const int* in_sizes, int n_in,
                              void* d_out, int out_size) {
    const float* x  = (const float*)d_in[0];   // [2,1024,64]
    const float* W1 = (const float*)d_in[1];   // [64,128]
    const float* b1 = (const float*)d_in[2];   // [64]
    const float* W2 = (const float*)d_in[3];   // [1,64]
    const float* b2 = (const float*)d_in[4];   // [1]
    const float* gu = (const float*)d_in[5];   // [1024,1024]
    float* out = (float*)d_out;                // [1024,1024] fp32

    k1_proj<<<256, 256>>>(x, W1, b1, W2, b2);
    k2_pair<<<dim3(16, 16), dim3(16, 16)>>>(W2, gu, out);
}